// round 4
// baseline (speedup 1.0000x reference)
#include <cuda_runtime.h>
#include <cuda_bf16.h>
#include <math.h>

#define OUTN 11008
#define INN  4096
#define MTOK 4096            // 2 * 2048 tokens
#define NTOT 45088768        // OUTN * INN
#define NCNT 1024
#define SPADU 40             // smem row stride in b16 units (64B data + 16B pad)
#define DSMEM (2*128*SPADU*2*2 + 128*128*4)   // 40960 + 65536 = 106496

// ---------------- scratch (static device globals; no allocation) ----------------
__device__ float          g_wt[NTOT];          // transformed/clipped weights (fp32)
__device__ signed char    g_wq8[NTOT];         // int4-valued weights as int8 (45MB)
__device__ signed char    g_xq8[MTOK * INN];   // int8 activations q (16MB)
__device__ signed char    g_xq8T[INN * MTOK];  // transposed activations (16MB)
__device__ unsigned short g_spk[NTOT];         // per-row sparse k indices
__device__ float          g_spd[NTOT];         // per-row sparse deltas
__device__ int            g_spcnt[OUTN];
__device__ float          g_wscale[OUTN];
__device__ float          g_ascale[MTOK];
__device__ float          g_rowabs[OUTN];
__device__ double         g_psum[OUTN];
__device__ double         g_psumsq[OUTN];
__device__ int            g_pcnt[NCNT];
__device__ float          g_stats[4];          // [0]=mean, [1]=T=3*std, [2]=is_like

// ---------------- K0: kronecker transform + clip + row stats ----------------
__global__ __launch_bounds__(256) void k_transform(
    const float* __restrict__ W, const float* __restrict__ L,
    const float* __restrict__ R, const float* __restrict__ cmax,
    const float* __restrict__ cmin)
{
    __shared__ double sAd[2048];   // 16KB, aliased as float sA[4096]
    __shared__ float  sL[4096];
    __shared__ float  sR[4096];
    float* sA = (float*)sAd;

    const int o   = blockIdx.x;
    const int tid = threadIdx.x;
    const int u   = tid >> 4;
    const int v   = tid & 15;

    const float* Wo = W + (size_t)o * INN;
    for (int i = tid; i < 4096; i += 256) { sA[i] = Wo[i]; sL[i] = L[i]; sR[i] = R[i]; }
    __syncthreads();

    float acc[4][4];
    #pragma unroll
    for (int j = 0; j < 4; j++)
        #pragma unroll
        for (int l = 0; l < 4; l++) acc[j][l] = 0.f;

    for (int b = 0; b < 64; b++) {
        float4 rr = *(const float4*)&sR[(b << 6) + (v << 2)];
        float  wr[4];
        #pragma unroll
        for (int j = 0; j < 4; j++) wr[j] = sA[(((u << 2) + j) << 6) + b];
        #pragma unroll
        for (int j = 0; j < 4; j++) {
            acc[j][0] = fmaf(wr[j], rr.x, acc[j][0]);
            acc[j][1] = fmaf(wr[j], rr.y, acc[j][1]);
            acc[j][2] = fmaf(wr[j], rr.z, acc[j][2]);
            acc[j][3] = fmaf(wr[j], rr.w, acc[j][3]);
        }
    }
    __syncthreads();
    #pragma unroll
    for (int j = 0; j < 4; j++)
        *(float4*)&sA[(((u << 2) + j) << 6) + (v << 2)] =
            make_float4(acc[j][0], acc[j][1], acc[j][2], acc[j][3]);
    __syncthreads();

    float vv[4][4];
    #pragma unroll
    for (int j = 0; j < 4; j++)
        #pragma unroll
        for (int l = 0; l < 4; l++) vv[j][l] = 0.f;

    for (int a = 0; a < 64; a++) {
        float4 td = *(const float4*)&sA[(a << 6) + (v << 2)];
        float4 lc = *(const float4*)&sL[(a << 6) + (u << 2)];
        float lcr[4] = {lc.x, lc.y, lc.z, lc.w};
        #pragma unroll
        for (int j = 0; j < 4; j++) {
            vv[j][0] = fmaf(lcr[j], td.x, vv[j][0]);
            vv[j][1] = fmaf(lcr[j], td.y, vv[j][1]);
            vv[j][2] = fmaf(lcr[j], td.z, vv[j][2]);
            vv[j][3] = fmaf(lcr[j], td.w, vv[j][3]);
        }
    }

    float lmin = 3.4e38f, lmax = -3.4e38f;
    #pragma unroll
    for (int j = 0; j < 4; j++)
        #pragma unroll
        for (int l = 0; l < 4; l++) { lmin = fminf(lmin, vv[j][l]); lmax = fmaxf(lmax, vv[j][l]); }

    __syncthreads();
    sR[tid] = lmin; sR[256 + tid] = lmax;
    __syncthreads();
    for (int s = 128; s > 0; s >>= 1) {
        if (tid < s) {
            sR[tid]       = fminf(sR[tid], sR[tid + s]);
            sR[256 + tid] = fmaxf(sR[256 + tid], sR[256 + tid + s]);
        }
        __syncthreads();
    }
    const float rmin = sR[0], rmax = sR[256];
    const float lo = rmin * (1.f / (1.f + expf(-cmin[o])));
    const float hi = rmax * (1.f / (1.f + expf(-cmax[o])));

    float la = 0.f; double ls = 0.0, lss = 0.0;
    #pragma unroll
    for (int j = 0; j < 4; j++)
        #pragma unroll
        for (int l = 0; l < 4; l++) {
            float w = fminf(fmaxf(vv[j][l], lo), hi);
            vv[j][l] = w;
            la = fmaxf(la, fabsf(w));
            ls += (double)w;
            lss += (double)w * (double)w;
        }

    __syncthreads();
    sAd[tid] = ls; sAd[256 + tid] = lss; sR[tid] = la;
    __syncthreads();
    for (int s = 128; s > 0; s >>= 1) {
        if (tid < s) {
            sAd[tid]       += sAd[tid + s];
            sAd[256 + tid] += sAd[256 + tid + s];
            sR[tid] = fmaxf(sR[tid], sR[tid + s]);
        }
        __syncthreads();
    }
    if (tid == 0) { g_psum[o] = sAd[0]; g_psumsq[o] = sAd[256]; g_rowabs[o] = sR[0]; }

    float* outp = g_wt + (size_t)o * INN;
    #pragma unroll
    for (int j = 0; j < 4; j++)
        *(float4*)&outp[(((u << 2) + j) << 6) + (v << 2)] =
            make_float4(vv[j][0], vv[j][1], vv[j][2], vv[j][3]);
}

// ---------------- K1: reduce per-row partials -> mean, T ----------------
__global__ __launch_bounds__(256) void k_stats1()
{
    __shared__ double ds[512];
    int tid = threadIdx.x;
    double s = 0.0, ss = 0.0;
    for (int i = tid; i < OUTN; i += 256) { s += g_psum[i]; ss += g_psumsq[i]; }
    ds[tid] = s; ds[256 + tid] = ss;
    __syncthreads();
    for (int st = 128; st > 0; st >>= 1) {
        if (tid < st) { ds[tid] += ds[tid + st]; ds[256 + tid] += ds[256 + tid + st]; }
        __syncthreads();
    }
    if (tid == 0) {
        double mean = ds[0] / (double)NTOT;
        double var  = ds[256] / (double)NTOT - mean * mean;
        if (var < 0.0) var = 0.0;
        g_stats[0] = (float)mean;
        g_stats[1] = (float)(3.0 * sqrt(var));
    }
}

// ---------------- K2: outlier count partials ----------------
__global__ __launch_bounds__(256) void k_count()
{
    const float mean = g_stats[0], T = g_stats[1];
    int cnt = 0;
    size_t stride = (size_t)gridDim.x * 256 * 4;
    for (size_t i = ((size_t)blockIdx.x * 256 + threadIdx.x) * 4; i < (size_t)NTOT; i += stride) {
        float4 w4 = *(const float4*)(g_wt + i);
        cnt += (fabsf(w4.x - mean) > T) + (fabsf(w4.y - mean) > T)
             + (fabsf(w4.z - mean) > T) + (fabsf(w4.w - mean) > T);
    }
    __shared__ int sc[256];
    sc[threadIdx.x] = cnt;
    __syncthreads();
    for (int s = 128; s > 0; s >>= 1) {
        if (threadIdx.x < s) sc[threadIdx.x] += sc[threadIdx.x + s];
        __syncthreads();
    }
    if (threadIdx.x == 0) g_pcnt[blockIdx.x] = sc[0];
}

// ---------------- K3: finalize frac -> is_like ----------------
__global__ __launch_bounds__(1024) void k_frac()
{
    __shared__ int sc[NCNT];
    int tid = threadIdx.x;
    sc[tid] = g_pcnt[tid];
    __syncthreads();
    for (int s = 512; s > 0; s >>= 1) {
        if (tid < s) sc[tid] += sc[tid + s];
        __syncthreads();
    }
    if (tid == 0) {
        float frac = (float)sc[0] / (float)NTOT;
        g_stats[2] = (frac > 1e-4f && frac < 0.05f) ? 1.f : 0.f;
    }
}

// ---------------- K4: per-row quantize -> int8 q + sparse (k, delta) list ----------------
__global__ __launch_bounds__(256) void k_wfinal()
{
    __shared__ int scnt[256];
    const int o   = blockIdx.x;
    const int tid = threadIdx.x;
    const float a1 = 0.01f;
    const float T = g_stats[1];
    const bool like = (g_stats[2] != 0.f);

    float ra = g_rowabs[o];
    float m = (like && ra > T) ? (T + (ra - T) * a1) : ra;   // fold monotone in |w|
    float scale = m / 7.0f + 1e-8f;
    if (tid == 0) g_wscale[o] = scale;

    const float* wrow = g_wt + (size_t)o * INN;

    union { int4 v; signed char b[16]; } qpack;
    float dl[16];
    unsigned tagmask = 0;
    int cnt = 0;

    #pragma unroll
    for (int g = 0; g < 4; g++) {
        float4 w4 = *(const float4*)(wrow + tid * 16 + g * 4);
        float wv[4] = {w4.x, w4.y, w4.z, w4.w};
        #pragma unroll
        for (int e = 0; e < 4; e++) {
            int idx = g * 4 + e;
            float w = wv[e];
            bool tg = like && (fabsf(w) > T);
            float win = tg ? copysignf(T + (fabsf(w) - T) * a1, w) : w;
            float q = fminf(fmaxf(rintf(win / scale), -7.f), 7.f);
            float wq = q * scale;
            float wfin = tg ? copysignf(T + (fabsf(wq) - T) / a1, w) : wq;
            qpack.b[idx] = (signed char)q;
            dl[idx] = wfin - wq;       // zero for untagged
            if (tg) { tagmask |= (1u << idx); cnt++; }
        }
    }
    *(int4*)(g_wq8 + (size_t)o * INN + tid * 16) = qpack.v;

    // deterministic block-wide exclusive scan of per-thread tag counts
    scnt[tid] = cnt;
    __syncthreads();
    for (int s = 1; s < 256; s <<= 1) {
        int v = 0;
        if (tid >= s) v = scnt[tid - s];
        __syncthreads();
        if (tid >= s) scnt[tid] += v;
        __syncthreads();
    }
    int off = scnt[tid] - cnt;
    if (tid == 255) g_spcnt[o] = scnt[255];

    unsigned short* kp = g_spk + (size_t)o * INN;
    float*          dp = g_spd + (size_t)o * INN;
    #pragma unroll
    for (int idx = 0; idx < 16; idx++) {
        if (tagmask & (1u << idx)) {
            kp[off] = (unsigned short)(tid * 16 + idx);
            dp[off] = dl[idx];
            off++;
        }
    }
}

// ---------------- K5: per-token activation fake-quant -> int8 + scale ----------------
__global__ __launch_bounds__(256) void k_actq(const float* __restrict__ X)
{
    __shared__ float red[256];
    int t = blockIdx.x, tid = threadIdx.x;
    const float* x = X + (size_t)t * INN;
    float4 vals[4];
    float la = 0.f;
    #pragma unroll
    for (int i = 0; i < 4; i++) {
        vals[i] = *(const float4*)&x[(tid + i * 256) * 4];
        la = fmaxf(la, fmaxf(fmaxf(fabsf(vals[i].x), fabsf(vals[i].y)),
                             fmaxf(fabsf(vals[i].z), fabsf(vals[i].w))));
    }
    red[tid] = la;
    __syncthreads();
    for (int s = 128; s > 0; s >>= 1) {
        if (tid < s) red[tid] = fmaxf(red[tid], red[tid + s]);
        __syncthreads();
    }
    const float scale = red[0] / 127.0f + 1e-8f;
    if (tid == 0) g_ascale[t] = scale;
    signed char* out = g_xq8 + (size_t)t * INN;
    #pragma unroll
    for (int i = 0; i < 4; i++) {
        float4 v = vals[i];
        union { int w; signed char b[4]; } p;
        p.b[0] = (signed char)fminf(fmaxf(rintf(v.x / scale), -127.f), 127.f);
        p.b[1] = (signed char)fminf(fmaxf(rintf(v.y / scale), -127.f), 127.f);
        p.b[2] = (signed char)fminf(fmaxf(rintf(v.z / scale), -127.f), 127.f);
        p.b[3] = (signed char)fminf(fmaxf(rintf(v.w / scale), -127.f), 127.f);
        *(int*)&out[(tid + i * 256) * 4] = p.w;
    }
}

// ---------------- K5b: transpose activations int8 [m][k] -> [k][m] ----------------
__global__ __launch_bounds__(256) void k_xT()
{
    __shared__ signed char ts[64][65];
    int k0 = blockIdx.x * 64, m0 = blockIdx.y * 64;
    int r  = threadIdx.x >> 2;
    int c4 = (threadIdx.x & 3) * 16;

    union { int4 v; signed char b[16]; } u;
    u.v = *(const int4*)(g_xq8 + (size_t)(m0 + r) * INN + k0 + c4);
    #pragma unroll
    for (int i = 0; i < 16; i++) ts[r][c4 + i] = u.b[i];
    __syncthreads();
    #pragma unroll
    for (int i = 0; i < 16; i++) u.b[i] = ts[c4 + i][r];
    *(int4*)(g_xq8T + (size_t)(k0 + r) * MTOK + m0 + c4) = u.v;
}

// ---------------- K6: int8 tensor-core GEMM + sparse outlier correction ----------------
__device__ __forceinline__ void cpasync16(unsigned saddr, const void* g)
{
    asm volatile("cp.async.ca.shared.global [%0], [%1], 16;\n" :: "r"(saddr), "l"(g));
}
__device__ __forceinline__ void ldsm4(unsigned* r, unsigned saddr)
{
    asm volatile("ldmatrix.sync.aligned.m8n8.x4.shared.b16 {%0,%1,%2,%3}, [%4];"
                 : "=r"(r[0]), "=r"(r[1]), "=r"(r[2]), "=r"(r[3]) : "r"(saddr));
}
__device__ __forceinline__ void mma16832(int* d, const unsigned* a, unsigned b0, unsigned b1)
{
    asm volatile("mma.sync.aligned.m16n8k32.row.col.s32.s8.s8.s32 "
                 "{%0,%1,%2,%3}, {%4,%5,%6,%7}, {%8,%9}, {%0,%1,%2,%3};"
                 : "+r"(d[0]), "+r"(d[1]), "+r"(d[2]), "+r"(d[3])
                 : "r"(a[0]), "r"(a[1]), "r"(a[2]), "r"(a[3]), "r"(b0), "r"(b1));
}

__global__ __launch_bounds__(256) void k_gemm_i8(const float* __restrict__ bias,
                                                 float* __restrict__ C)
{
    extern __shared__ char dsm[];
    unsigned short* sA   = (unsigned short*)dsm;                     // [2][128*SPADU]
    unsigned short* sB   = (unsigned short*)(dsm + 2 * 128 * SPADU * 2);
    float*          corrS = (float*)(dsm + 4 * 128 * SPADU * 2);     // [128][128]

    const int tid  = threadIdx.x;
    const int lane = tid & 31;
    const int wid  = tid >> 5;
    const int wm   = wid & 1;       // 2 warps in M
    const int wn   = wid >> 1;      // 4 warps in N
    const int bn   = blockIdx.x * 128;
    const int bm   = blockIdx.y * 128;

    const int lrow = tid >> 2;           // 0..63
    const int lcolb = (tid & 3) * 16;    // byte col 0,16,32,48
    const int lcolu = (tid & 3) * 8;     // b16-unit col

    for (int i = tid; i < 128 * 128; i += 256) corrS[i] = 0.f;

    int acc[4][4][4];
    #pragma unroll
    for (int i = 0; i < 4; i++)
        #pragma unroll
        for (int j = 0; j < 4; j++)
            #pragma unroll
            for (int l = 0; l < 4; l++) acc[i][j][l] = 0;

    const signed char* Abase = g_xq8 + (size_t)bm * INN;
    const signed char* Bbase = g_wq8 + (size_t)bn * INN;

    auto load_tile = [&](int it, int buf) {
        int k = it * 64;
        #pragma unroll
        for (int i = 0; i < 2; i++) {
            int row = lrow + i * 64;
            cpasync16((unsigned)__cvta_generic_to_shared(
                          &sA[buf * 128 * SPADU + row * SPADU + lcolu]),
                      Abase + (size_t)row * INN + k + lcolb);
            cpasync16((unsigned)__cvta_generic_to_shared(
                          &sB[buf * 128 * SPADU + row * SPADU + lcolu]),
                      Bbase + (size_t)row * INN + k + lcolb);
        }
    };

    const int KITERS = INN / 64;   // 64
    load_tile(0, 0);
    asm volatile("cp.async.commit_group;\n");

    for (int it = 0; it < KITERS; ++it) {
        int buf = it & 1;
        if (it + 1 < KITERS) {
            load_tile(it + 1, buf ^ 1);
            asm volatile("cp.async.commit_group;\n");
            asm volatile("cp.async.wait_group 1;\n");
        } else {
            asm volatile("cp.async.wait_group 0;\n");
        }
        __syncthreads();

        unsigned short* sAb = sA + buf * 128 * SPADU;
        unsigned short* sBb = sB + buf * 128 * SPADU;

        #pragma unroll
        for (int ks = 0; ks < 2; ks++) {
            unsigned afr[4][4], bfr[2][4];
            int arow = wm * 64 + (lane & 15);
            int acol = ks * 16 + (lane >> 4) * 8;
            #pragma unroll
            for (int mb = 0; mb < 4; mb++)
                ldsm4(afr[mb], (unsigned)__cvta_generic_to_shared(
                          &sAb[(arow + mb * 16) * SPADU + acol]));
            int brow = wn * 32 + (lane & 7) + ((lane >> 4) & 1) * 8;
            int bcol = ks * 16 + ((lane >> 3) & 1) * 8;
            #pragma unroll
            for (int nb = 0; nb < 2; nb++)
                ldsm4(bfr[nb], (unsigned)__cvta_generic_to_shared(
                          &sBb[(brow + nb * 16) * SPADU + bcol]));
            #pragma unroll
            for (int mb = 0; mb < 4; mb++)
                #pragma unroll
                for (int f = 0; f < 4; f++)
                    mma16832(acc[mb][f], afr[mb],
                             bfr[f >> 1][(f & 1) * 2], bfr[f >> 1][(f & 1) * 2 + 1]);
        }
        __syncthreads();
    }

    // ---- sparse outlier correction: warp wid owns n_local [wid*16, wid*16+16) ----
    for (int j = 0; j < 16; j++) {
        int nl = wid * 16 + j;
        int n  = bn + nl;
        int cnt = g_spcnt[n];
        const unsigned short* kp = g_spk + (size_t)n * INN;
        const float*          dp = g_spd + (size_t)n * INN;
        for (int t = 0; t < cnt; t++) {
            int k = kp[t];
            float delta = dp[t];
            const signed char* col = g_xq8T + (size_t)k * MTOK + bm;
            #pragma unroll
            for (int i = 0; i < 4; i++) {
                float qv = (float)col[lane + 32 * i];
                corrS[nl * 128 + lane + 32 * i] += qv * delta;
            }
        }
    }
    __syncthreads();

    // ---- epilogue: out = as_m * (ws_n * acc + corr) + bias ----
    #pragma unroll
    for (int mb = 0; mb < 4; mb++) {
        int ml0 = wm * 64 + mb * 16 + (lane >> 2);
        int m0  = bm + ml0;
        float as0 = g_ascale[m0];
        float as1 = g_ascale[m0 + 8];
        #pragma unroll
        for (int f = 0; f < 4; f++) {
            int gnl = wn * 32 + f * 8 + (lane & 3) * 2;
            int gn  = bn + gnl;
            float ws0 = g_wscale[gn], ws1 = g_wscale[gn + 1];
            float b0 = bias[gn], b1 = bias[gn + 1];
            float c00 = corrS[gnl * 128 + ml0];
            float c01 = corrS[(gnl + 1) * 128 + ml0];
            float c10 = corrS[gnl * 128 + ml0 + 8];
            float c11 = corrS[(gnl + 1) * 128 + ml0 + 8];
            float2 o0 = make_float2(as0 * (ws0 * (float)acc[mb][f][0] + c00) + b0,
                                    as0 * (ws1 * (float)acc[mb][f][1] + c01) + b1);
            float2 o1 = make_float2(as1 * (ws0 * (float)acc[mb][f][2] + c10) + b0,
                                    as1 * (ws1 * (float)acc[mb][f][3] + c11) + b1);
            *(float2*)(C + (size_t)m0 * OUTN + gn)       = o0;
            *(float2*)(C + (size_t)(m0 + 8) * OUTN + gn) = o1;
        }
    }
}

// ---------------- launch ----------------
extern "C" void kernel_launch(void* const* d_in, const int* in_sizes, int n_in,
                              void* d_out, int out_size)
{
    const float* hs   = (const float*)d_in[0];  // (2,2048,4096)
    const float* w    = (const float*)d_in[1];  // (11008,4096)
    const float* bias = (const float*)d_in[2];  // (11008)
    const float* tl   = (const float*)d_in[3];  // (64,64)
    const float* tr   = (const float*)d_in[4];  // (64,64)
    const float* cmax = (const float*)d_in[5];  // (11008,1)
    const float* cmin = (const float*)d_in[6];  // (11008,1)
    float* out = (float*)d_out;

    static bool attr_set = false;
    if (!attr_set) {
        cudaFuncSetAttribute(k_gemm_i8, cudaFuncAttributeMaxDynamicSharedMemorySize, DSMEM);
        attr_set = true;
    }

    k_transform<<<OUTN, 256>>>(w, tl, tr, cmax, cmin);
    k_stats1<<<1, 256>>>();
    k_count<<<NCNT, 256>>>();
    k_frac<<<1, 1024>>>();
    k_wfinal<<<OUTN, 256>>>();
    k_actq<<<MTOK, 256>>>(hs);
    dim3 gt(INN / 64, MTOK / 64);
    k_xT<<<gt, 256>>>();
    dim3 g(OUTN / 128, MTOK / 128);
    k_gemm_i8<<<g, 256, DSMEM>>>(bias, out);
}

// round 6
// speedup vs baseline: 1.6587x; 1.6587x over previous
#include <cuda_runtime.h>
#include <cuda_bf16.h>
#include <math.h>

#define OUTN 11008
#define INN  4096
#define MTOK 4096            // 2 * 2048 tokens
#define NTOT 45088768        // OUTN * INN
#define NCNT 1024
#define SPADU 40             // smem row stride in b16 units (64B data + 16B pad)

// ---------------- scratch (static device globals; no allocation) ----------------
__device__ float          g_wt[NTOT];          // transformed/clipped weights (fp32)
__device__ signed char    g_wq8[NTOT];         // int4-valued weights as int8
__device__ signed char    g_xq8[MTOK * INN];   // int8 activations q
__device__ signed char    g_xq8T[INN * MTOK];  // transposed activations [k][m]
__device__ unsigned short g_spk[NTOT];         // per-row sparse k indices
__device__ float          g_spd[NTOT];         // per-row sparse deltas
__device__ int            g_spcnt[OUTN];
__device__ float          g_wscale[OUTN];
__device__ float          g_ascale[MTOK];
__device__ float          g_rowabs[OUTN];
__device__ double         g_psum[OUTN];
__device__ double         g_psumsq[OUTN];
__device__ int            g_pcnt[NCNT];
__device__ float          g_stats[4];          // [0]=mean, [1]=T=3*std, [2]=is_like

// ---------------- K0: kronecker transform + clip + row stats ----------------
__global__ __launch_bounds__(256) void k_transform(
    const float* __restrict__ W, const float* __restrict__ L,
    const float* __restrict__ R, const float* __restrict__ cmax,
    const float* __restrict__ cmin)
{
    __shared__ double sAd[2048];
    __shared__ float  sL[4096];
    __shared__ float  sR[4096];
    float* sA = (float*)sAd;

    const int o   = blockIdx.x;
    const int tid = threadIdx.x;
    const int u   = tid >> 4;
    const int v   = tid & 15;

    const float* Wo = W + (size_t)o * INN;
    for (int i = tid; i < 4096; i += 256) { sA[i] = Wo[i]; sL[i] = L[i]; sR[i] = R[i]; }
    __syncthreads();

    float acc[4][4];
    #pragma unroll
    for (int j = 0; j < 4; j++)
        #pragma unroll
        for (int l = 0; l < 4; l++) acc[j][l] = 0.f;

    for (int b = 0; b < 64; b++) {
        float4 rr = *(const float4*)&sR[(b << 6) + (v << 2)];
        float  wr[4];
        #pragma unroll
        for (int j = 0; j < 4; j++) wr[j] = sA[(((u << 2) + j) << 6) + b];
        #pragma unroll
        for (int j = 0; j < 4; j++) {
            acc[j][0] = fmaf(wr[j], rr.x, acc[j][0]);
            acc[j][1] = fmaf(wr[j], rr.y, acc[j][1]);
            acc[j][2] = fmaf(wr[j], rr.z, acc[j][2]);
            acc[j][3] = fmaf(wr[j], rr.w, acc[j][3]);
        }
    }
    __syncthreads();
    #pragma unroll
    for (int j = 0; j < 4; j++)
        *(float4*)&sA[(((u << 2) + j) << 6) + (v << 2)] =
            make_float4(acc[j][0], acc[j][1], acc[j][2], acc[j][3]);
    __syncthreads();

    float vv[4][4];
    #pragma unroll
    for (int j = 0; j < 4; j++)
        #pragma unroll
        for (int l = 0; l < 4; l++) vv[j][l] = 0.f;

    for (int a = 0; a < 64; a++) {
        float4 td = *(const float4*)&sA[(a << 6) + (v << 2)];
        float4 lc = *(const float4*)&sL[(a << 6) + (u << 2)];
        float lcr[4] = {lc.x, lc.y, lc.z, lc.w};
        #pragma unroll
        for (int j = 0; j < 4; j++) {
            vv[j][0] = fmaf(lcr[j], td.x, vv[j][0]);
            vv[j][1] = fmaf(lcr[j], td.y, vv[j][1]);
            vv[j][2] = fmaf(lcr[j], td.z, vv[j][2]);
            vv[j][3] = fmaf(lcr[j], td.w, vv[j][3]);
        }
    }

    float lmin = 3.4e38f, lmax = -3.4e38f;
    #pragma unroll
    for (int j = 0; j < 4; j++)
        #pragma unroll
        for (int l = 0; l < 4; l++) { lmin = fminf(lmin, vv[j][l]); lmax = fmaxf(lmax, vv[j][l]); }

    __syncthreads();
    sR[tid] = lmin; sR[256 + tid] = lmax;
    __syncthreads();
    for (int s = 128; s > 0; s >>= 1) {
        if (tid < s) {
            sR[tid]       = fminf(sR[tid], sR[tid + s]);
            sR[256 + tid] = fmaxf(sR[256 + tid], sR[256 + tid + s]);
        }
        __syncthreads();
    }
    const float rmin = sR[0], rmax = sR[256];
    const float lo = rmin * (1.f / (1.f + expf(-cmin[o])));
    const float hi = rmax * (1.f / (1.f + expf(-cmax[o])));

    float la = 0.f; double ls = 0.0, lss = 0.0;
    #pragma unroll
    for (int j = 0; j < 4; j++)
        #pragma unroll
        for (int l = 0; l < 4; l++) {
            float w = fminf(fmaxf(vv[j][l], lo), hi);
            vv[j][l] = w;
            la = fmaxf(la, fabsf(w));
            ls += (double)w;
            lss += (double)w * (double)w;
        }

    __syncthreads();
    sAd[tid] = ls; sAd[256 + tid] = lss; sR[tid] = la;
    __syncthreads();
    for (int s = 128; s > 0; s >>= 1) {
        if (tid < s) {
            sAd[tid]       += sAd[tid + s];
            sAd[256 + tid] += sAd[256 + tid + s];
            sR[tid] = fmaxf(sR[tid], sR[tid + s]);
        }
        __syncthreads();
    }
    if (tid == 0) { g_psum[o] = sAd[0]; g_psumsq[o] = sAd[256]; g_rowabs[o] = sR[0]; }

    float* outp = g_wt + (size_t)o * INN;
    #pragma unroll
    for (int j = 0; j < 4; j++)
        *(float4*)&outp[(((u << 2) + j) << 6) + (v << 2)] =
            make_float4(vv[j][0], vv[j][1], vv[j][2], vv[j][3]);
}

// ---------------- K1: reduce per-row partials -> mean, T ----------------
__global__ __launch_bounds__(256) void k_stats1()
{
    __shared__ double ds[512];
    int tid = threadIdx.x;
    double s = 0.0, ss = 0.0;
    for (int i = tid; i < OUTN; i += 256) { s += g_psum[i]; ss += g_psumsq[i]; }
    ds[tid] = s; ds[256 + tid] = ss;
    __syncthreads();
    for (int st = 128; st > 0; st >>= 1) {
        if (tid < st) { ds[tid] += ds[tid + st]; ds[256 + tid] += ds[256 + tid + st]; }
        __syncthreads();
    }
    if (tid == 0) {
        double mean = ds[0] / (double)NTOT;
        double var  = ds[256] / (double)NTOT - mean * mean;
        if (var < 0.0) var = 0.0;
        g_stats[0] = (float)mean;
        g_stats[1] = (float)(3.0 * sqrt(var));
    }
}

// ---------------- K2: outlier count partials ----------------
__global__ __launch_bounds__(256) void k_count()
{
    const float mean = g_stats[0], T = g_stats[1];
    int cnt = 0;
    size_t stride = (size_t)gridDim.x * 256 * 4;
    for (size_t i = ((size_t)blockIdx.x * 256 + threadIdx.x) * 4; i < (size_t)NTOT; i += stride) {
        float4 w4 = *(const float4*)(g_wt + i);
        cnt += (fabsf(w4.x - mean) > T) + (fabsf(w4.y - mean) > T)
             + (fabsf(w4.z - mean) > T) + (fabsf(w4.w - mean) > T);
    }
    __shared__ int sc[256];
    sc[threadIdx.x] = cnt;
    __syncthreads();
    for (int s = 128; s > 0; s >>= 1) {
        if (threadIdx.x < s) sc[threadIdx.x] += sc[threadIdx.x + s];
        __syncthreads();
    }
    if (threadIdx.x == 0) g_pcnt[blockIdx.x] = sc[0];
}

// ---------------- K3: finalize frac -> is_like ----------------
__global__ __launch_bounds__(1024) void k_frac()
{
    __shared__ int sc[NCNT];
    int tid = threadIdx.x;
    sc[tid] = g_pcnt[tid];
    __syncthreads();
    for (int s = 512; s > 0; s >>= 1) {
        if (tid < s) sc[tid] += sc[tid + s];
        __syncthreads();
    }
    if (tid == 0) {
        float frac = (float)sc[0] / (float)NTOT;
        g_stats[2] = (frac > 1e-4f && frac < 0.05f) ? 1.f : 0.f;
    }
}

// ---------------- K4: per-row quantize -> int8 q + sparse (k, delta) list ----------------
__global__ __launch_bounds__(256) void k_wfinal()
{
    __shared__ int scnt[256];
    const int o   = blockIdx.x;
    const int tid = threadIdx.x;
    const float a1 = 0.01f;
    const float T = g_stats[1];
    const bool like = (g_stats[2] != 0.f);

    float ra = g_rowabs[o];
    float m = (like && ra > T) ? (T + (ra - T) * a1) : ra;   // fold monotone in |w|
    float scale = m / 7.0f + 1e-8f;
    if (tid == 0) g_wscale[o] = scale;

    const float* wrow = g_wt + (size_t)o * INN;

    union { int4 v; signed char b[16]; } qpack;
    float dl[16];
    unsigned tagmask = 0;
    int cnt = 0;

    #pragma unroll
    for (int g = 0; g < 4; g++) {
        float4 w4 = *(const float4*)(wrow + tid * 16 + g * 4);
        float wv[4] = {w4.x, w4.y, w4.z, w4.w};
        #pragma unroll
        for (int e = 0; e < 4; e++) {
            int idx = g * 4 + e;
            float w = wv[e];
            bool tg = like && (fabsf(w) > T);
            float win = tg ? copysignf(T + (fabsf(w) - T) * a1, w) : w;
            float q = fminf(fmaxf(rintf(win / scale), -7.f), 7.f);
            float wq = q * scale;
            float wfin = tg ? copysignf(T + (fabsf(wq) - T) / a1, w) : wq;
            qpack.b[idx] = (signed char)q;
            dl[idx] = wfin - wq;       // zero for untagged
            if (tg) { tagmask |= (1u << idx); cnt++; }
        }
    }
    *(int4*)(g_wq8 + (size_t)o * INN + tid * 16) = qpack.v;

    scnt[tid] = cnt;
    __syncthreads();
    for (int s = 1; s < 256; s <<= 1) {
        int v = 0;
        if (tid >= s) v = scnt[tid - s];
        __syncthreads();
        if (tid >= s) scnt[tid] += v;
        __syncthreads();
    }
    int off = scnt[tid] - cnt;
    if (tid == 255) g_spcnt[o] = scnt[255];

    unsigned short* kp = g_spk + (size_t)o * INN;
    float*          dp = g_spd + (size_t)o * INN;
    #pragma unroll
    for (int idx = 0; idx < 16; idx++) {
        if (tagmask & (1u << idx)) {
            kp[off] = (unsigned short)(tid * 16 + idx);
            dp[off] = dl[idx];
            off++;
        }
    }
}

// ---------------- K5: per-token activation fake-quant -> int8 + scale ----------------
__global__ __launch_bounds__(256) void k_actq(const float* __restrict__ X)
{
    __shared__ float red[256];
    int t = blockIdx.x, tid = threadIdx.x;
    const float* x = X + (size_t)t * INN;
    float4 vals[4];
    float la = 0.f;
    #pragma unroll
    for (int i = 0; i < 4; i++) {
        vals[i] = *(const float4*)&x[(tid + i * 256) * 4];
        la = fmaxf(la, fmaxf(fmaxf(fabsf(vals[i].x), fabsf(vals[i].y)),
                             fmaxf(fabsf(vals[i].z), fabsf(vals[i].w))));
    }
    red[tid] = la;
    __syncthreads();
    for (int s = 128; s > 0; s >>= 1) {
        if (tid < s) red[tid] = fmaxf(red[tid], red[tid + s]);
        __syncthreads();
    }
    const float scale = red[0] / 127.0f + 1e-8f;
    if (tid == 0) g_ascale[t] = scale;
    signed char* out = g_xq8 + (size_t)t * INN;
    #pragma unroll
    for (int i = 0; i < 4; i++) {
        float4 v = vals[i];
        union { int w; signed char b[4]; } p;
        p.b[0] = (signed char)fminf(fmaxf(rintf(v.x / scale), -127.f), 127.f);
        p.b[1] = (signed char)fminf(fmaxf(rintf(v.y / scale), -127.f), 127.f);
        p.b[2] = (signed char)fminf(fmaxf(rintf(v.z / scale), -127.f), 127.f);
        p.b[3] = (signed char)fminf(fmaxf(rintf(v.w / scale), -127.f), 127.f);
        *(int*)&out[(tid + i * 256) * 4] = p.w;
    }
}

// ---------------- K5b: transpose activations int8 [m][k] -> [k][m] ----------------
__global__ __launch_bounds__(256) void k_xT()
{
    __shared__ signed char ts[64][65];
    int k0 = blockIdx.x * 64, m0 = blockIdx.y * 64;
    int r  = threadIdx.x >> 2;
    int c4 = (threadIdx.x & 3) * 16;

    union { int4 v; signed char b[16]; } u;
    u.v = *(const int4*)(g_xq8 + (size_t)(m0 + r) * INN + k0 + c4);
    #pragma unroll
    for (int i = 0; i < 16; i++) ts[r][c4 + i] = u.b[i];
    __syncthreads();
    #pragma unroll
    for (int i = 0; i < 16; i++) u.b[i] = ts[c4 + i][r];
    *(int4*)(g_xq8T + (size_t)(k0 + r) * MTOK + m0 + c4) = u.v;
}

// ---------------- K6: int8 IMMA GEMM + register-resident sparse correction ----------------
__device__ __forceinline__ void cpasync16(unsigned saddr, const void* g)
{
    asm volatile("cp.async.ca.shared.global [%0], [%1], 16;\n" :: "r"(saddr), "l"(g));
}
__device__ __forceinline__ void ldsm4(unsigned* r, unsigned saddr)
{
    asm volatile("ldmatrix.sync.aligned.m8n8.x4.shared.b16 {%0,%1,%2,%3}, [%4];"
                 : "=r"(r[0]), "=r"(r[1]), "=r"(r[2]), "=r"(r[3]) : "r"(saddr));
}
__device__ __forceinline__ void mma16832(int* d, const unsigned* a, unsigned b0, unsigned b1)
{
    asm volatile("mma.sync.aligned.m16n8k32.row.col.s32.s8.s8.s32 "
                 "{%0,%1,%2,%3}, {%4,%5,%6,%7}, {%8,%9}, {%0,%1,%2,%3};"
                 : "+r"(d[0]), "+r"(d[1]), "+r"(d[2]), "+r"(d[3])
                 : "r"(a[0]), "r"(a[1]), "r"(a[2]), "r"(a[3]), "r"(b0), "r"(b1));
}

__global__ __launch_bounds__(256, 2) void k_gemm_i8(const float* __restrict__ bias,
                                                    float* __restrict__ C)
{
    __shared__ unsigned short sA[2][128 * SPADU];
    __shared__ unsigned short sB[2][128 * SPADU];

    const int tid  = threadIdx.x;
    const int lane = tid & 31;
    const int wid  = tid >> 5;
    const int wm   = wid & 1;       // 2 warps in M
    const int wn   = wid >> 1;      // 4 warps in N
    const int bn   = blockIdx.x * 128;
    const int bm   = blockIdx.y * 128;

    const int lrow  = tid >> 2;          // 0..63
    const int lcolb = (tid & 3) * 16;    // byte col
    const int lcolu = (tid & 3) * 8;     // b16-unit col

    int acc[4][4][4];
    #pragma unroll
    for (int i = 0; i < 4; i++)
        #pragma unroll
        for (int j = 0; j < 4; j++)
            #pragma unroll
            for (int l = 0; l < 4; l++) acc[i][j][l] = 0;

    const signed char* Abase = g_xq8 + (size_t)bm * INN;
    const signed char* Bbase = g_wq8 + (size_t)bn * INN;

    auto load_tile = [&](int it, int buf) {
        int k = it * 64;
        #pragma unroll
        for (int i = 0; i < 2; i++) {
            int row = lrow + i * 64;
            cpasync16((unsigned)__cvta_generic_to_shared(&sA[buf][row * SPADU + lcolu]),
                      Abase + (size_t)row * INN + k + lcolb);
            cpasync16((unsigned)__cvta_generic_to_shared(&sB[buf][row * SPADU + lcolu]),
                      Bbase + (size_t)row * INN + k + lcolb);
        }
    };

    const int KITERS = INN / 64;   // 64
    load_tile(0, 0);
    asm volatile("cp.async.commit_group;\n");

    for (int it = 0; it < KITERS; ++it) {
        int buf = it & 1;
        if (it + 1 < KITERS) {
            load_tile(it + 1, buf ^ 1);
            asm volatile("cp.async.commit_group;\n");
            asm volatile("cp.async.wait_group 1;\n");
        } else {
            asm volatile("cp.async.wait_group 0;\n");
        }
        __syncthreads();

        #pragma unroll
        for (int ks = 0; ks < 2; ks++) {
            unsigned afr[4][4], bfr[2][4];
            int arow = wm * 64 + (lane & 15);
            int acol = ks * 16 + (lane >> 4) * 8;
            #pragma unroll
            for (int mb = 0; mb < 4; mb++)
                ldsm4(afr[mb], (unsigned)__cvta_generic_to_shared(
                          &sA[buf][(arow + mb * 16) * SPADU + acol]));
            int brow = wn * 32 + (lane & 7) + ((lane >> 4) & 1) * 8;
            int bcol = ks * 16 + ((lane >> 3) & 1) * 8;
            #pragma unroll
            for (int nb = 0; nb < 2; nb++)
                ldsm4(bfr[nb], (unsigned)__cvta_generic_to_shared(
                          &sB[buf][(brow + nb * 16) * SPADU + bcol]));
            #pragma unroll
            for (int mb = 0; mb < 4; mb++)
                #pragma unroll
                for (int f = 0; f < 4; f++)
                    mma16832(acc[mb][f], afr[mb],
                             bfr[f >> 1][(f & 1) * 2], bfr[f >> 1][(f & 1) * 2 + 1]);
        }
        __syncthreads();
    }

    // ---- convert to float with per-n weight scale ----
    float facc[4][4][4];
    #pragma unroll
    for (int f = 0; f < 4; f++) {
        int n0 = bn + wn * 32 + f * 8 + (lane & 3) * 2;
        float ws0 = g_wscale[n0], ws1 = g_wscale[n0 + 1];
        #pragma unroll
        for (int mb = 0; mb < 4; mb++) {
            facc[mb][f][0] = ws0 * (float)acc[mb][f][0];
            facc[mb][f][1] = ws1 * (float)acc[mb][f][1];
            facc[mb][f][2] = ws0 * (float)acc[mb][f][2];
            facc[mb][f][3] = ws1 * (float)acc[mb][f][3];
        }
    }

    // ---- sparse outlier correction: each lane owns its own n columns ----
    // lane's columns: n = bn + wn*32 + f*8 + (lane&3)*2 + l, its m rows: (lane>>2)+16*mb (+8)
    const int mofs = bm + wm * 64 + (lane >> 2);
    #pragma unroll
    for (int f = 0; f < 4; f++) {
        #pragma unroll
        for (int l = 0; l < 2; l++) {
            int n = bn + wn * 32 + f * 8 + (lane & 3) * 2 + l;
            int cnt = g_spcnt[n];
            const unsigned short* kp = g_spk + (size_t)n * INN;
            const float*          dp = g_spd + (size_t)n * INN;
            for (int t = 0; t < cnt; t++) {
                int k = kp[t];
                float delta = dp[t];
                const signed char* col = g_xq8T + (size_t)k * MTOK + mofs;
                #pragma unroll
                for (int mb = 0; mb < 4; mb++) {
                    facc[mb][f][l]     += (float)col[mb * 16]     * delta;
                    facc[mb][f][l + 2] += (float)col[mb * 16 + 8] * delta;
                }
            }
        }
    }

    // ---- epilogue: out = as_m * facc + bias ----
    #pragma unroll
    for (int mb = 0; mb < 4; mb++) {
        int m0 = bm + wm * 64 + mb * 16 + (lane >> 2);
        float as0 = g_ascale[m0];
        float as1 = g_ascale[m0 + 8];
        #pragma unroll
        for (int f = 0; f < 4; f++) {
            int gn = bn + wn * 32 + f * 8 + (lane & 3) * 2;
            float b0 = bias[gn], b1 = bias[gn + 1];
            float2 o0 = make_float2(as0 * facc[mb][f][0] + b0,
                                    as0 * facc[mb][f][1] + b1);
            float2 o1 = make_float2(as1 * facc[mb][f][2] + b0,
                                    as1 * facc[mb][f][3] + b1);
            *(float2*)(C + (size_t)m0 * OUTN + gn)       = o0;
            *(float2*)(C + (size_t)(m0 + 8) * OUTN + gn) = o1;
        }
    }
}

// ---------------- launch ----------------
extern "C" void kernel_launch(void* const* d_in, const int* in_sizes, int n_in,
                              void* d_out, int out_size)
{
    const float* hs   = (const float*)d_in[0];  // (2,2048,4096)
    const float* w    = (const float*)d_in[1];  // (11008,4096)
    const float* bias = (const float*)d_in[2];  // (11008)
    const float* tl   = (const float*)d_in[3];  // (64,64)
    const float* tr   = (const float*)d_in[4];  // (64,64)
    const float* cmax = (const float*)d_in[5];  // (11008,1)
    const float* cmin = (const float*)d_in[6];  // (11008,1)
    float* out = (float*)d_out;

    k_transform<<<OUTN, 256>>>(w, tl, tr, cmax, cmin);
    k_stats1<<<1, 256>>>();
    k_count<<<NCNT, 256>>>();
    k_frac<<<1, 1024>>>();
    k_wfinal<<<OUTN, 256>>>();
    k_actq<<<MTOK, 256>>>(hs);
    dim3 gt(INN / 64, MTOK / 64);
    k_xT<<<gt, 256>>>();
    dim3 g(OUTN / 128, MTOK / 128);
    k_gemm_i8<<<g, 256>>>(bias, out);
}